// round 15
// baseline (speedup 1.0000x reference)
#include <cuda_runtime.h>

#define KK 9
#define TPB 256
#define GRID 740                   /* 5 CTAs/SM x 148 = exactly one wave */
#define RPT 512                    /* rows per tile (2 per thread: tid, tid+256) */
#define TILE_N (RPT * KK)          /* 4608 floats */
#define TILE_F4 (TILE_N / 4)       /* 1152 float4 = 18432 B */

__device__ float g_part[GRID];
__device__ unsigned g_ticket = 0;

__device__ __forceinline__ float ex2f(float x) { float r; asm("ex2.approx.f32 %0,%1;" : "=f"(r) : "f"(x)); return r; }
__device__ __forceinline__ float lg2f(float x) { float r; asm("lg2.approx.f32 %0,%1;" : "=f"(r) : "f"(x)); return r; }
__device__ __forceinline__ float rcpf(float x) { float r; asm("rcp.approx.f32 %0,%1;" : "=f"(r) : "f"(x)); return r; }

__device__ __forceinline__ void cpa16(unsigned dst, const float4* src) {
    asm volatile("cp.async.cg.shared.global [%0], [%1], 16;" :: "r"(dst), "l"(src));
}
#define CP_COMMIT() asm volatile("cp.async.commit_group;")
#define CP_WAIT1()  asm volatile("cp.async.wait_group 1;")

#define LOG2E 1.4426950408889634f
#define LN2   0.6931471805599453f

__device__ __forceinline__ void stage(float* buf, const float* logits, int t, int tid) {
    unsigned sb = (unsigned)__cvta_generic_to_shared(buf);
    const float4* g = (const float4*)logits + (size_t)t * TILE_F4;
    cpa16(sb + (unsigned)tid * 16u,          g + tid);
    cpa16(sb + (unsigned)(tid + 256) * 16u,  g + tid + 256);
    cpa16(sb + (unsigned)(tid + 512) * 16u,  g + tid + 512);
    cpa16(sb + (unsigned)(tid + 768) * 16u,  g + tid + 768);
    if (tid < TILE_F4 - 1024)
        cpa16(sb + (unsigned)(tid + 1024) * 16u, g + tid + 1024);
}

// Scalar row loss (remainder path only).
__device__ __forceinline__ float row_loss_s(const float* l, int yi, float lyv,
                                            float aL, float aR,
                                            const float2* twc, float Wy) {
    const float cwv[KK] = {3.f/95.f, 7.f/95.f, 10.f/95.f, 10.f/95.f, 10.f/95.f,
                           10.f/95.f, 10.f/95.f, 10.f/95.f, 25.f/95.f};
    const float2* tw = twc + yi * KK;
    float C = 0.f, tail = 0.f, fr = 0.f, A = 0.f, Bm = 0.f;
#pragma unroll
    for (int k = 0; k < KK; k++) {
        float e = ex2f(l[k] * LOG2E);
        C += e;
        float2 w = tw[k];
        tail = fmaf(e, w.x, tail);
        if (w.x > 0.f) fr = fmaxf(fr, e);
        A  = fmaf(cwv[k], C * C, A);
        Bm = fmaf(w.y, C, Bm);
    }
    float S = C;
    float ey = ex2f(lyv * LOG2E);
    float en = ex2f(fmaxf(aL, aR) * LOG2E);
    float invS = rcpf(S);
    float nll  = lg2f(S) * LN2 - lyv;
    float fm   = fmaxf(fmaf(fr - ey, invS, 0.15f), 0.f);
    float lp   = fmaxf(fmaf(en - ey, invS, 0.35f), 0.f);
    float emd_u = fmaf(Wy, S * S, fmaf(Bm, -(S + S), A));
    float r = fmaf(nll, 0.45511961331341866f, 2.8f * fm);
    r = fmaf(tail * invS, 3.6f, r);
    r = fmaf(lp, 4.8f, r);
    r = fmaf(emd_u * invS * invS, 0.48f, r);
    return r;
}

__global__ void __launch_bounds__(TPB, 5)
loss_kernel(const float* __restrict__ logits, const int* __restrict__ y,
            float* __restrict__ out, int B, float invB) {
    __shared__ float  sbuf[2][TILE_N];     // 2 x 18432 B double buffer
    __shared__ float2 stwc[KK * KK];       // {tail weight, cw_k*[k<=y]}
    __shared__ float  swyp[KK];            // Wy + 15/95 (EMD delta fold)
    __shared__ float  wsum[TPB / 32];
    __shared__ int    s_last;

    int tid = threadIdx.x;

    if (tid < KK * KK) {
        int yy = tid / KK, kk = tid % KK;
        int d = kk - yy; if (d < 0) d = -d;
        int dm1 = d - 1;
        float tw = (d > 1) ? (float)(dm1 * dm1 * dm1) : 0.f;
        float wk = (kk == 0) ? 3.f/95.f : (kk == 1) ? 7.f/95.f : (kk == 8) ? 25.f/95.f : 10.f/95.f;
        stwc[tid] = make_float2(tw, (kk <= yy) ? wk : 0.f);
    }
    if (tid < KK) {
        float s = 0.f;
        for (int k = 0; k <= tid; k++)
            s += (k == 0) ? 3.f/95.f : (k == 1) ? 7.f/95.f : (k == 8) ? 25.f/95.f : 10.f/95.f;
        swyp[tid] = s + 15.f/95.f;
    }

    int nT = B / RPT;
    float acc = 0.f;

    int t  = blockIdx.x;        bool v  = (t  < nT);
    int tn = t + GRID;          bool vn = (tn < nT);
    if (v)  stage(sbuf[0], logits, t,  tid);
    CP_COMMIT();
    if (vn) stage(sbuf[1], logits, tn, tid);
    CP_COMMIT();
    int yc0 = 0, yc1 = 0;
    if (v) { yc0 = y[t * RPT + tid]; yc1 = y[t * RPT + 256 + tid]; }

    int cur = 0;
    while (v) {
        CP_WAIT1();
        __syncthreads();                   // buf[cur] fully staged

        const float* r0p = sbuf[cur] + tid * KK;          // stride 9: conflict-free
        const float* r1p = sbuf[cur] + (tid + 256) * KK;
        int yi0 = yc0, yi1 = yc1;
        const float2* tw0 = stwc + yi0 * KK;
        const float2* tw1 = stwc + yi1 * KK;

        // neighbor / label logits (dynamic LDS while buf valid)
        int il0 = yi0 > 0 ? yi0 - 1 : 0, ir0 = yi0 < KK-1 ? yi0 + 1 : KK-1;
        int il1 = yi1 > 0 ? yi1 - 1 : 0, ir1 = yi1 < KK-1 ? yi1 + 1 : KK-1;
        float lyv0 = r0p[yi0];
        float aL0 = (yi0 > 0)    ? r0p[il0] : -1e30f;
        float aR0 = (yi0 < KK-1) ? r0p[ir0] : -1e30f;
        float lyv1 = r1p[yi1];
        float aL1 = (yi1 > 0)    ? r1p[il1] : -1e30f;
        float aR1 = (yi1 < KK-1) ? r1p[ir1] : -1e30f;

        // prefetch next labels (LDG latency hidden under compute)
        int yn0 = 0, yn1 = 0;
        if (vn) { yn0 = y[tn * RPT + tid]; yn1 = y[tn * RPT + 256 + tid]; }

        // ---- 2-row loss, streaming logits from smem (no register tile) ----
        float C0 = 0.f, C1 = 0.f, q0 = 0.f, q1 = 0.f;
        float Bm0 = 0.f, Bm1 = 0.f, tail0 = 0.f, tail1 = 0.f;
        float far0 = 0.f, far1 = 0.f;
        float c00 = 0.f, c01 = 0.f, c10 = 0.f, c11 = 0.f;
#pragma unroll
        for (int k = 0; k < KK; k++) {
            float e0 = ex2f(r0p[k] * LOG2E);
            float e1 = ex2f(r1p[k] * LOG2E);
            C0 += e0; C1 += e1;
            q0 = fmaf(C0, C0, q0);
            q1 = fmaf(C1, C1, q1);
            float2 w0 = tw0[k], w1 = tw1[k];       // LDS.64, broadcast-cheap
            Bm0 = fmaf(w0.y, C0, Bm0);
            Bm1 = fmaf(w1.y, C1, Bm1);
            tail0 = fmaf(e0, w0.x, tail0);
            tail1 = fmaf(e1, w1.x, tail1);
            if (w0.x > 0.f) far0 = fmaxf(far0, e0);
            if (w1.x > 0.f) far1 = fmaxf(far1, e1);
            if (k == 0) { c00 = C0; c01 = C1; }
            if (k == 1) { c10 = C0; c11 = C1; }
        }
        __syncthreads();                   // all reads of buf[cur] done

        // stage tile t+2*GRID into the buffer we just drained
        int tnn = tn + GRID; bool vnn = vn && (tnn < nT);
        if (vnn) stage(sbuf[cur], logits, tnn, tid);
        CP_COMMIT();

        // ---- epilogue (py eliminated: fm/lp via (x - ey)*invS + c) ----
        {
            float ey = ex2f(lyv0 * LOG2E);
            float en = ex2f(fmaxf(aL0, aR0) * LOG2E);
            float invS = rcpf(C0);
            float nll = lg2f(C0) * LN2 - lyv0;
            float fm = fmaxf(fmaf(far0 - ey, invS, 0.15f), 0.f);
            float lp = fmaxf(fmaf(en   - ey, invS, 0.35f), 0.f);
            float emd_u = fmaf(swyp[yi0], C0 * C0, fmaf(Bm0, -(C0 + C0),
                          fmaf(10.f/95.f, q0, fmaf(-7.f/95.f, c00 * c00, -3.f/95.f * (c10 * c10)))));
            float r = fmaf(nll, 0.45511961331341866f, 2.8f * fm);
            r = fmaf(tail0 * invS, 3.6f, r);
            r = fmaf(lp, 4.8f, r);
            r = fmaf(emd_u * invS * invS, 0.48f, r);
            acc += r;
        }
        {
            float ey = ex2f(lyv1 * LOG2E);
            float en = ex2f(fmaxf(aL1, aR1) * LOG2E);
            float invS = rcpf(C1);
            float nll = lg2f(C1) * LN2 - lyv1;
            float fm = fmaxf(fmaf(far1 - ey, invS, 0.15f), 0.f);
            float lp = fmaxf(fmaf(en   - ey, invS, 0.35f), 0.f);
            float emd_u = fmaf(swyp[yi1], C1 * C1, fmaf(Bm1, -(C1 + C1),
                          fmaf(10.f/95.f, q1, fmaf(-7.f/95.f, c01 * c01, -3.f/95.f * (c11 * c11)))));
            float r = fmaf(nll, 0.45511961331341866f, 2.8f * fm);
            r = fmaf(tail1 * invS, 3.6f, r);
            r = fmaf(lp, 4.8f, r);
            r = fmaf(emd_u * invS * invS, 0.48f, r);
            acc += r;
        }

        t = tn; v = vn; tn = tnn; vn = vnn; yc0 = yn0; yc1 = yn1; cur ^= 1;
    }

    // remainder rows (B % RPT) — block 0, direct global loads
    int rem = nT * RPT;
    if (blockIdx.x == 0) {
        for (int row = rem + tid; row < B; row += TPB) {
            float l[KK];
#pragma unroll
            for (int k = 0; k < KK; k++) l[k] = logits[(size_t)row * KK + k];
            int yi = y[row];
            float lyv = l[0], aL = -1e30f, aR = -1e30f;
#pragma unroll
            for (int k = 0; k < KK; k++) {
                lyv = (k == yi)     ? l[k] : lyv;
                aL  = (k == yi - 1) ? l[k] : aL;
                aR  = (k == yi + 1) ? l[k] : aR;
            }
            acc += row_loss_s(l, yi, lyv, aL, aR, stwc, swyp[yi] - 15.f/95.f);
        }
    }

    // deterministic block reduction
#pragma unroll
    for (int o = 16; o > 0; o >>= 1) acc += __shfl_xor_sync(0xffffffffu, acc, o);
    if ((tid & 31) == 0) wsum[tid >> 5] = acc;
    __syncthreads();
    if (tid == 0) {
        float s = 0.f;
#pragma unroll
        for (int i = 0; i < TPB / 32; i++) s += wsum[i];
        g_part[blockIdx.x] = s;
        __threadfence();
        unsigned tk = atomicAdd(&g_ticket, 1u);
        s_last = (tk == GRID - 1);
    }
    __syncthreads();

    if (s_last) {
        __threadfence();
        float s = 0.f;
        for (int i = tid; i < GRID; i += TPB) s += __ldcg(&g_part[i]);
#pragma unroll
        for (int o = 16; o > 0; o >>= 1) s += __shfl_xor_sync(0xffffffffu, s, o);
        if ((tid & 31) == 0) wsum[tid >> 5] = s;
        __syncthreads();
        if (tid == 0) {
            float tt = 0.f;
#pragma unroll
            for (int i = 0; i < TPB / 32; i++) tt += wsum[i];
            out[0] = tt * invB;
            g_ticket = 0;   // deterministic across graph replays
        }
    }
}

extern "C" void kernel_launch(void* const* d_in, const int* in_sizes, int n_in,
                              void* d_out, int out_size) {
    const float* logits = (const float*)d_in[0];
    const int*   y      = (const int*)d_in[1];
    int B = in_sizes[1];
    loss_kernel<<<GRID, TPB>>>(logits, y, (float*)d_out, B, 1.f / (float)B);
}